// round 1
// baseline (speedup 1.0000x reference)
#include <cuda_runtime.h>
#include <cuda_bf16.h>
#include <math_constants.h>

#define BATCH 8
#define NPTS 2048
#define KNN 16
#define TPB 256
#define TILES (NPTS / TPB)   // 8 point-tiles per batch

// partials[cloud][batch][tile] — written fully every launch, no zeroing needed
__device__ float g_partials[2 * BATCH * TILES];

__global__ __launch_bounds__(TPB, 1)
void knn_partial_kernel(const float* __restrict__ seed,
                        const float* __restrict__ gts) {
    __shared__ float4 sp[NPTS];            // 32 KB: all points of one (cloud,batch)
    __shared__ float red[TPB / 32];

    const int tile = blockIdx.x;
    const int b    = blockIdx.y;
    const int c    = blockIdx.z;
    const int tid  = threadIdx.x;

    const float* __restrict__ src = (c == 0 ? seed : gts) + (size_t)b * NPTS * 3;

    // Stage all 2048 points as float4 for single LDS.128 per j in the hot loop.
    for (int j = tid; j < NPTS; j += TPB) {
        float x = src[3 * j + 0];
        float y = src[3 * j + 1];
        float z = src[3 * j + 2];
        sp[j] = make_float4(x, y, z, 0.0f);
    }
    __syncthreads();

    const int i = tile * TPB + tid;
    const float4 pi = sp[i];

    // Sorted-ascending top-16 in registers (static indices only -> no spills).
    float r[KNN];
#pragma unroll
    for (int k = 0; k < KNN; k++) r[k] = CUDART_INF_F;

#pragma unroll 4
    for (int j = 0; j < NPTS; j++) {
        const float4 pj = sp[j];          // broadcast load (same addr all lanes)
        const float dx = pj.x - pi.x;
        const float dy = pj.y - pi.y;
        const float dz = pj.z - pi.z;
        const float d = fmaf(dx, dx, fmaf(dy, dy, dz * dz));
        if (d < r[KNN - 1]) {
            // insert d, evict current max; preserves ascending order
            float t = d;
#pragma unroll
            for (int k = 0; k < KNN; k++) {
                const float lo = fminf(r[k], t);
                const float hi = fmaxf(r[k], t);
                r[k] = lo;
                t = hi;
            }
        }
    }

    float s = 0.0f;
#pragma unroll
    for (int k = 0; k < KNN; k++) s += r[k];

    // Deterministic block reduction: warp shuffle, then cross-warp via smem.
#pragma unroll
    for (int off = 16; off > 0; off >>= 1)
        s += __shfl_down_sync(0xffffffffu, s, off);
    if ((tid & 31) == 0) red[tid >> 5] = s;
    __syncthreads();
    if (tid == 0) {
        float bs = 0.0f;
#pragma unroll
        for (int w = 0; w < TPB / 32; w++) bs += red[w];
        g_partials[(c * BATCH + b) * TILES + tile] = bs;
    }
}

__global__ void finish_kernel(float* __restrict__ out) {
    if (threadIdx.x != 0 || blockIdx.x != 0) return;
    double loss = 0.0;
    const double norm = 1.0 / ((double)NPTS * (double)KNN);
    for (int b = 0; b < BATCH; b++) {
        double s0 = 0.0, s1 = 0.0;
        for (int t = 0; t < TILES; t++) {
            s0 += (double)g_partials[(0 * BATCH + b) * TILES + t];
            s1 += (double)g_partials[(1 * BATCH + b) * TILES + t];
        }
        const double diff = (s0 - s1) * norm;
        loss += diff * diff;
    }
    out[0] = (float)(loss / (double)BATCH);
}

extern "C" void kernel_launch(void* const* d_in, const int* in_sizes, int n_in,
                              void* d_out, int out_size) {
    const float* seed = (const float*)d_in[0];
    const float* gts  = (const float*)d_in[1];
    float* out = (float*)d_out;

    dim3 grid(TILES, BATCH, 2);
    knn_partial_kernel<<<grid, TPB>>>(seed, gts);
    finish_kernel<<<1, 32>>>(out);
}